// round 4
// baseline (speedup 1.0000x reference)
#include <cuda_runtime.h>
#include <cstdint>

#define TT   512
#define BB   128
#define NIN  256
#define NH   1024
#define NOUT 32

// ---------------- device scratch ----------------
__device__ unsigned int g_idx[TT * BB * 64];      // per (t,b): up to 256 uint8 indices
__device__ int          g_cnt[TT * BB];
__device__ unsigned int g_zbits[TT * BB * 32];    // word w bit p <-> h = w*32+p (natural layout)
__device__ float        g_whT[NIN * NH];          // w_h transposed [i][h]

// ---------------- transpose w_h [H][I] -> [I][H] ----------------
__global__ void transpose_wh_kernel(const float* __restrict__ w_h) {
    int k = blockIdx.x * blockDim.x + threadIdx.x;
    if (k < NH * NIN) {
        int h = k >> 8;
        int i = k & 255;
        g_whT[i * NH + h] = w_h[k];
    }
}

// ---------------- compact: warp per (t,b), no smem, no block barrier ----------------
__global__ __launch_bounds__(256) void compact_kernel(const float* __restrict__ spikes) {
    int gw   = (blockIdx.x * blockDim.x + threadIdx.x) >> 5;   // global warp id
    int lane = threadIdx.x & 31;
    const int NW = 8192;   // 1024 blocks * 8 warps

    for (int u = gw; u < TT * BB; u += NW) {
        const float4* p = (const float4*)(spikes + (size_t)u * NIN) + lane * 2;
        float4 a = __ldcs(p);
        float4 b = __ldcs(p + 1);
        unsigned m8 = 0;
        m8 |= (a.x != 0.f) ? 1u   : 0u;
        m8 |= (a.y != 0.f) ? 2u   : 0u;
        m8 |= (a.z != 0.f) ? 4u   : 0u;
        m8 |= (a.w != 0.f) ? 8u   : 0u;
        m8 |= (b.x != 0.f) ? 16u  : 0u;
        m8 |= (b.y != 0.f) ? 32u  : 0u;
        m8 |= (b.z != 0.f) ? 64u  : 0u;
        m8 |= (b.w != 0.f) ? 128u : 0u;

        int c  = __popc(m8);
        int sc = c;                                   // inclusive scan
#pragma unroll
        for (int off = 1; off < 32; off <<= 1) {
            int n = __shfl_up_sync(0xffffffffu, sc, off);
            if (lane >= off) sc += n;
        }
        int tot = __shfl_sync(0xffffffffu, sc, 31);
        int ex  = sc - c;                             // exclusive

        unsigned char* outp = (unsigned char*)g_idx + (size_t)u * 256 + ex;
        int base_i = lane << 3;
        unsigned mm = m8;
        int k = 0;
        while (mm) {
            int j = __ffs(mm) - 1; mm &= mm - 1;
            outp[k++] = (unsigned char)(base_i + j);
        }
        if (lane == 31) g_cnt[u] = tot;
    }
}

// ---------------- fused sparse projection + CUBA LIF scan ----------------
// Grid (32,16): bx = 32-h tile, by = 8-batch group. Block 256 = 8 warps.
// Warp = one (batch, htile); lane owns h = h0 + lane. smem tile 32 KB, 6 CTAs/SM,
// all 512 CTAs resident in one wave. Single fp32 chain in index order.
#define LIF_SMEM (256 * 32 * 4)

__global__ __launch_bounds__(256, 6) void lif_kernel() {
    extern __shared__ float s_w[];   // [i*32 + u] = whT[i][h0+u]
    int tid = threadIdx.x;
    int h0  = blockIdx.x << 5;
    int b0  = blockIdx.y << 3;

    for (int k = tid; k < 256 * 32; k += 256)
        s_w[k] = g_whT[(k >> 5) * NH + h0 + (k & 31)];
    __syncthreads();   // only barrier

    int u  = tid & 31;
    int b  = b0 + (tid >> 5);
    const float* wrow = s_w + u;

    size_t tb = (size_t)b;
    uint4 p0 = ((const uint4*)(g_idx + tb * 64))[0];
    uint4 p1 = ((const uint4*)(g_idx + tb * 64))[1];
    int cnt_n = g_cnt[tb];

    float v = 0.f, cur = 0.f;

    for (int t = 0; t < TT; t++) {
        uint4 q0 = p0, q1 = p1;
        int cnt = cnt_n;
        size_t tbn = tb + BB;
        if (t + 1 < TT) {           // prefetch next step's index list
            p0 = ((const uint4*)(g_idx + tbn * 64))[0];
            p1 = ((const uint4*)(g_idx + tbn * 64))[1];
            cnt_n = g_cnt[tbn];
        }

        unsigned w8[8] = {q0.x, q0.y, q0.z, q0.w, q1.x, q1.y, q1.z, q1.w};
        int nw = cnt >> 2;

        float c = 0.f;   // single chain, exact index order
#pragma unroll
        for (int kw = 0; kw < 8; kw++) {
            if (kw >= nw) break;
            unsigned wd = w8[kw];
            c += wrow[(wd & 255u) << 5];
            c += wrow[((wd >> 8) & 255u) << 5];
            c += wrow[((wd >> 16) & 255u) << 5];
            c += wrow[(wd >> 24) << 5];
        }
        for (int kw = 8; kw < nw; kw++) {   // rare (>32 actives)
            unsigned wd = g_idx[tb * 64 + kw];
            c += wrow[(wd & 255u) << 5];
            c += wrow[((wd >> 8) & 255u) << 5];
            c += wrow[((wd >> 16) & 255u) << 5];
            c += wrow[(wd >> 24) << 5];
        }
        int rem = cnt & 3;
        if (rem) {
            unsigned wd;
            if (nw >= 8) {
                wd = g_idx[tb * 64 + nw];
            } else {
                wd = w8[0];
#pragma unroll
                for (int k = 1; k < 8; k++) if (nw == k) wd = w8[k];
            }
            c += wrow[(wd & 255u) << 5];
            if (rem > 1) c += wrow[((wd >> 8) & 255u) << 5];
            if (rem > 2) c += wrow[((wd >> 16) & 255u) << 5];
        }

        // CUBA LIF (exact fp32, mirrors reference)
        cur = cur * 0.875f + c;
        v   = v + 0.125f * (cur - v);
        bool z = (v - 1.0f) > 0.0f;
        if (z) v = 0.0f;

        unsigned mz = __ballot_sync(0xffffffffu, z);
        if (u == 0) g_zbits[tb * 32 + blockIdx.x] = mz;   // natural layout

        tb = tbn;
    }
}

// ---------------- output currents + fused LI scan ----------------
// Grid 128 (block per batch), 1024 threads = 32 warps (2x R2's latency hiding).
// smem: w_oT pad-33 [1024][33] + c buffer [512][32] = 200704 B, 1 CTA/SM.
#define COUT_SMEM (NH * 33 * 4 + TT * NOUT * 4)

__global__ __launch_bounds__(1024, 1) void cout_li_kernel(const float* __restrict__ w_o,
                                                          float* __restrict__ out) {
    extern __shared__ float smem[];
    float* s_wT = smem;              // [h*33 + o]
    float* s_c  = smem + NH * 33;    // [t*32 + o]
    int tid = threadIdx.x;

    for (int k = tid; k < NOUT * NH; k += 1024) {
        int o = k >> 10;
        int h = k & 1023;
        s_wT[h * 33 + o] = w_o[k];
    }
    __syncthreads();

    int b = blockIdx.x;
    int warp = tid >> 5, lane = tid & 31;

    for (int t = warp; t < TT; t += 32) {
        unsigned m = g_zbits[((size_t)t * BB + b) * 32 + lane];
        float c0 = 0.f, c1 = 0.f;
#pragma unroll
        for (int wi = 0; wi < 32; wi++) {
            unsigned mw = __shfl_sync(0xffffffffu, m, wi);
            int base = wi * (32 * 33) + lane;         // h = wi*32 + p
            while (mw) {
                int p = __ffs(mw) - 1; mw &= mw - 1;
                c0 += s_wT[base + p * 33];
                if (mw) {
                    int p2 = __ffs(mw) - 1; mw &= mw - 1;
                    c1 += s_wT[base + p2 * 33];
                }
            }
        }
        s_c[t * 32 + lane] = c0 + c1;
    }
    __syncthreads();

    // fused CUBA LI readout: warp 0 scans time, lane = output neuron
    if (warp == 0) {
        float v = 0.f, cur = 0.f;
        float cb[4];
#pragma unroll
        for (int j = 0; j < 4; j++) cb[j] = s_c[j * 32 + lane];
        for (int t0 = 0; t0 < TT; t0 += 4) {
            float cn[4];
            if (t0 + 4 < TT) {
#pragma unroll
                for (int j = 0; j < 4; j++) cn[j] = s_c[(t0 + 4 + j) * 32 + lane];
            }
#pragma unroll
            for (int j = 0; j < 4; j++) {
                cur = cur * 0.875f + cb[j];
                v = v + 0.125f * (cur - v);
                out[((size_t)(t0 + j) * BB + b) * 32 + lane] = v;
            }
#pragma unroll
            for (int j = 0; j < 4; j++) cb[j] = cn[j];
        }
    }
}

// ---------------- launch ----------------
extern "C" void kernel_launch(void* const* d_in, const int* in_sizes, int n_in,
                              void* d_out, int out_size) {
    const float* spikes = (const float*)d_in[0];   // [512,128,256]
    const float* w_h    = (const float*)d_in[1];   // [1024,256]
    const float* w_o    = (const float*)d_in[2];   // [32,1024]
    float* out = (float*)d_out;                    // [512,128,32]

    cudaFuncSetAttribute(lif_kernel,     cudaFuncAttributeMaxDynamicSharedMemorySize, LIF_SMEM);
    cudaFuncSetAttribute(cout_li_kernel, cudaFuncAttributeMaxDynamicSharedMemorySize, COUT_SMEM);

    transpose_wh_kernel<<<(NH * NIN + 1023) / 1024, 1024>>>(w_h);
    compact_kernel<<<1024, 256>>>(spikes);
    lif_kernel<<<dim3(32, 16), 256, LIF_SMEM>>>();
    cout_li_kernel<<<BB, 1024, COUT_SMEM>>>(w_o, out);
}

// round 5
// speedup vs baseline: 1.5417x; 1.5417x over previous
#include <cuda_runtime.h>
#include <cstdint>

#define TT   512
#define BB   128
#define NIN  256
#define NH   1024
#define NOUT 32

// ---------------- device scratch ----------------
__device__ unsigned int g_idx[TT * BB * 64];      // per (t,b): up to 256 uint8 indices
__device__ int          g_cnt[TT * BB];
__device__ unsigned int g_zbits[TT * BB * 32];    // word w bit p <-> h = w*32+p (natural)
__device__ float        g_whT[NIN * NH];          // w_h transposed [i][h]

// ---------------- transpose w_h [H][I] -> [I][H] ----------------
__global__ void transpose_wh_kernel(const float* __restrict__ w_h) {
    int k = blockIdx.x * blockDim.x + threadIdx.x;
    if (k < NH * NIN) {
        int h = k >> 8;
        int i = k & 255;
        g_whT[i * NH + h] = w_h[k];
    }
}

// ---------------- compact: warp per (t,b), no smem, no block barrier ----------------
__global__ __launch_bounds__(256) void compact_kernel(const float* __restrict__ spikes) {
    int gw   = (blockIdx.x * blockDim.x + threadIdx.x) >> 5;
    int lane = threadIdx.x & 31;
    const int NW = 8192;   // 1024 blocks * 8 warps

    for (int u = gw; u < TT * BB; u += NW) {
        const float4* p = (const float4*)(spikes + (size_t)u * NIN) + lane * 2;
        float4 a = __ldcs(p);
        float4 b = __ldcs(p + 1);
        unsigned m8 = 0;
        m8 |= (a.x != 0.f) ? 1u   : 0u;
        m8 |= (a.y != 0.f) ? 2u   : 0u;
        m8 |= (a.z != 0.f) ? 4u   : 0u;
        m8 |= (a.w != 0.f) ? 8u   : 0u;
        m8 |= (b.x != 0.f) ? 16u  : 0u;
        m8 |= (b.y != 0.f) ? 32u  : 0u;
        m8 |= (b.z != 0.f) ? 64u  : 0u;
        m8 |= (b.w != 0.f) ? 128u : 0u;

        int c  = __popc(m8);
        int sc = c;
#pragma unroll
        for (int off = 1; off < 32; off <<= 1) {
            int n = __shfl_up_sync(0xffffffffu, sc, off);
            if (lane >= off) sc += n;
        }
        int tot = __shfl_sync(0xffffffffu, sc, 31);
        int ex  = sc - c;

        unsigned char* outp = (unsigned char*)g_idx + (size_t)u * 256 + ex;
        int base_i = lane << 3;
        unsigned mm = m8;
        int k = 0;
        while (mm) {
            int j = __ffs(mm) - 1; mm &= mm - 1;
            outp[k++] = (unsigned char)(base_i + j);
        }
        if (lane == 31) g_cnt[u] = tot;
    }
}

// ---------------- fused sparse projection + CUBA LIF scan ----------------
// Grid (8,16): bx = 128-h tile, by = 8-batch group. Block 256 = 8 warps.
// Warp = (batch, htile); lane owns 4 h via one LDS.128 per active input.
// Permuted tile: s_w[i*128 + lane*4 + j] = whT[i][h0 + 32*j + lane]
//   -> float4 component j maps to h = h0 + 32*j + lane, so ballot(z_j) is
//      exactly natural-layout word (h0/32 + j). smem 128 KB, 1 CTA/SM.
#define LIF_SMEM (NIN * 128 * 4)

__global__ __launch_bounds__(256) void lif_kernel() {
    extern __shared__ float s_w[];
    int tid = threadIdx.x;
    int h0  = blockIdx.x << 7;
    int b0  = blockIdx.y << 3;

    // coalesced read, permuted write (setup-only bank conflicts are fine)
    for (int k = tid; k < NIN * 128; k += 256) {
        int i = k >> 7, m = k & 127;
        float w = g_whT[i * NH + h0 + m];
        s_w[(i << 7) + ((m & 31) << 2) + (m >> 5)] = w;
    }
    __syncthreads();   // only barrier

    int lane = tid & 31;
    int b    = b0 + (tid >> 5);
    const float4* wrow = (const float4*)s_w + lane;

    size_t tb = (size_t)b;
    uint4 p0 = ((const uint4*)(g_idx + tb * 64))[0];
    uint4 p1 = ((const uint4*)(g_idx + tb * 64))[1];
    int cnt_n = g_cnt[tb];

    float v0 = 0.f, v1 = 0.f, v2 = 0.f, v3 = 0.f;
    float i0 = 0.f, i1 = 0.f, i2 = 0.f, i3 = 0.f;

    for (int t = 0; t < TT; t++) {
        uint4 q0 = p0, q1 = p1;
        int cnt = cnt_n;
        size_t tbn = tb + BB;
        if (t + 1 < TT) {                    // prefetch next step's list
            p0 = ((const uint4*)(g_idx + tbn * 64))[0];
            p1 = ((const uint4*)(g_idx + tbn * 64))[1];
            cnt_n = g_cnt[tbn];
        }

        unsigned w8[8] = {q0.x, q0.y, q0.z, q0.w, q1.x, q1.y, q1.z, q1.w};
        int nw = cnt >> 2;

        float c0 = 0.f, c1 = 0.f, c2 = 0.f, c3 = 0.f;  // per-h chains, index order
#pragma unroll
        for (int kw = 0; kw < 8; kw++) {
            if (kw >= nw) break;
            unsigned wd = w8[kw];
#pragma unroll
            for (int s = 0; s < 4; s++) {
                float4 f = wrow[((wd >> (8 * s)) & 255u) << 5];
                c0 += f.x; c1 += f.y; c2 += f.z; c3 += f.w;
            }
        }
        for (int kw = 8; kw < nw; kw++) {    // rare (>32 actives)
            unsigned wd = g_idx[tb * 64 + kw];
#pragma unroll
            for (int s = 0; s < 4; s++) {
                float4 f = wrow[((wd >> (8 * s)) & 255u) << 5];
                c0 += f.x; c1 += f.y; c2 += f.z; c3 += f.w;
            }
        }
        int rem = cnt & 3;
        if (rem) {
            unsigned wd;
            if (nw >= 8) {
                wd = g_idx[tb * 64 + nw];
            } else {
                wd = w8[0];
#pragma unroll
                for (int k = 1; k < 8; k++) if (nw == k) wd = w8[k];
            }
#pragma unroll
            for (int s = 0; s < 3; s++) {
                if (s < rem) {
                    float4 f = wrow[((wd >> (8 * s)) & 255u) << 5];
                    c0 += f.x; c1 += f.y; c2 += f.z; c3 += f.w;
                }
            }
        }

        // CUBA LIF (exact fp32, mirrors reference op order)
        i0 = i0 * 0.875f + c0;  v0 = v0 + 0.125f * (i0 - v0);
        i1 = i1 * 0.875f + c1;  v1 = v1 + 0.125f * (i1 - v1);
        i2 = i2 * 0.875f + c2;  v2 = v2 + 0.125f * (i2 - v2);
        i3 = i3 * 0.875f + c3;  v3 = v3 + 0.125f * (i3 - v3);
        bool z0 = (v0 - 1.0f) > 0.0f; if (z0) v0 = 0.f;
        bool z1 = (v1 - 1.0f) > 0.0f; if (z1) v1 = 0.f;
        bool z2 = (v2 - 1.0f) > 0.0f; if (z2) v2 = 0.f;
        bool z3 = (v3 - 1.0f) > 0.0f; if (z3) v3 = 0.f;

        uint4 mz;
        mz.x = __ballot_sync(0xffffffffu, z0);
        mz.y = __ballot_sync(0xffffffffu, z1);
        mz.z = __ballot_sync(0xffffffffu, z2);
        mz.w = __ballot_sync(0xffffffffu, z3);
        if (lane == 0)
            *(uint4*)(g_zbits + tb * 32 + (blockIdx.x << 2)) = mz;

        tb = tbn;
    }
}

// ---------------- output currents + fused LI scan (R4 version, 72 us) ----------------
#define COUT_SMEM (NH * 33 * 4 + TT * NOUT * 4)

__global__ __launch_bounds__(1024, 1) void cout_li_kernel(const float* __restrict__ w_o,
                                                          float* __restrict__ out) {
    extern __shared__ float smem[];
    float* s_wT = smem;              // [h*33 + o]
    float* s_c  = smem + NH * 33;    // [t*32 + o]
    int tid = threadIdx.x;

    for (int k = tid; k < NOUT * NH; k += 1024) {
        int o = k >> 10;
        int h = k & 1023;
        s_wT[h * 33 + o] = w_o[k];
    }
    __syncthreads();

    int b = blockIdx.x;
    int warp = tid >> 5, lane = tid & 31;

    for (int t = warp; t < TT; t += 32) {
        unsigned m = g_zbits[((size_t)t * BB + b) * 32 + lane];
        float c0 = 0.f, c1 = 0.f;
#pragma unroll
        for (int wi = 0; wi < 32; wi++) {
            unsigned mw = __shfl_sync(0xffffffffu, m, wi);
            int base = wi * (32 * 33) + lane;
            while (mw) {
                int p = __ffs(mw) - 1; mw &= mw - 1;
                c0 += s_wT[base + p * 33];
                if (mw) {
                    int p2 = __ffs(mw) - 1; mw &= mw - 1;
                    c1 += s_wT[base + p2 * 33];
                }
            }
        }
        s_c[t * 32 + lane] = c0 + c1;
    }
    __syncthreads();

    if (warp == 0) {
        float v = 0.f, cur = 0.f;
        float cb[4];
#pragma unroll
        for (int j = 0; j < 4; j++) cb[j] = s_c[j * 32 + lane];
        for (int t0 = 0; t0 < TT; t0 += 4) {
            float cn[4];
            if (t0 + 4 < TT) {
#pragma unroll
                for (int j = 0; j < 4; j++) cn[j] = s_c[(t0 + 4 + j) * 32 + lane];
            }
#pragma unroll
            for (int j = 0; j < 4; j++) {
                cur = cur * 0.875f + cb[j];
                v = v + 0.125f * (cur - v);
                out[((size_t)(t0 + j) * BB + b) * 32 + lane] = v;
            }
#pragma unroll
            for (int j = 0; j < 4; j++) cb[j] = cn[j];
        }
    }
}

// ---------------- launch ----------------
extern "C" void kernel_launch(void* const* d_in, const int* in_sizes, int n_in,
                              void* d_out, int out_size) {
    const float* spikes = (const float*)d_in[0];   // [512,128,256]
    const float* w_h    = (const float*)d_in[1];   // [1024,256]
    const float* w_o    = (const float*)d_in[2];   // [32,1024]
    float* out = (float*)d_out;                    // [512,128,32]

    cudaFuncSetAttribute(lif_kernel,     cudaFuncAttributeMaxDynamicSharedMemorySize, LIF_SMEM);
    cudaFuncSetAttribute(cout_li_kernel, cudaFuncAttributeMaxDynamicSharedMemorySize, COUT_SMEM);

    transpose_wh_kernel<<<(NH * NIN + 1023) / 1024, 1024>>>(w_h);
    compact_kernel<<<1024, 256>>>(spikes);
    lif_kernel<<<dim3(NH / 128, BB / 8), 256, LIF_SMEM>>>();
    cout_li_kernel<<<BB, 1024, COUT_SMEM>>>(w_o, out);
}